// round 15
// baseline (speedup 1.0000x reference)
#include <cuda_runtime.h>
#include <stdint.h>

#define FEAT   256
#define NCLS   100
#define KSEL   16
#define NMAX   100000
#define BMAX   512
#define BTHREADS 256

// Scratch (no cudaMalloc allowed).
__device__ float g_sum[NMAX + BMAX];
__device__ int   g_cls[BMAX];

// ---------------------------------------------------------------------------
// Kernel A: row sums in LLVM/aarch64 loop-vectorizer order with the CORRECT
// AArch64 interleave factor: VF=4, IC=2 (AArch64TTI::getMaxInterleaveFactor
// == 2 — my R11/R13 used IC=4, an x86-ism).
//   a0 += x[8i .. 8i+3], a1 += x[8i+4 .. 8i+7]   (sequential over i=0..31)
//   c = a0 + a1                                   (single part combine)
//   tot = (c0+c1) + (c2+c3)                       (NEON faddp pairwise)
// One thread per row; float4 loads; adds in exactly this order.
// Tested & rejected (two output clusters):
//   cluster1 = 9.075846e-3 (ONE flip): strict seq (R10), float4-pairwise (R8)
//   cluster2 = 5.023952e-2 (~5 flips): GPU vec2 tree (R9), NEON IC4 variants
//   (R11, R13)
// Next queue: GPU 256thr scalar 8-warp ((W0+W4)+(W2+W6))+((W1+W5)+(W3+W7));
//             SVE-predicated variant.
// ---------------------------------------------------------------------------
__global__ void row_sums_kernel(const float* __restrict__ x,
                                const float* __restrict__ features,
                                int N, int B) {
    int r = blockIdx.x * blockDim.x + threadIdx.x;
    int rows = N + B;
    if (r >= rows) return;

    const float* src = (r < N) ? (features + (size_t)r * FEAT)
                               : (x + (size_t)(r - N) * FEAT);
    const float4* v = (const float4*)src;

    float4 a0 = make_float4(0.f, 0.f, 0.f, 0.f);
    float4 a1 = a0;
    #pragma unroll
    for (int i = 0; i < FEAT / 8; i++) {           // 32 blocks of 8 elements
        float4 q0 = v[2 * i + 0];
        float4 q1 = v[2 * i + 1];
        a0.x = __fadd_rn(a0.x, q0.x); a0.y = __fadd_rn(a0.y, q0.y);
        a0.z = __fadd_rn(a0.z, q0.z); a0.w = __fadd_rn(a0.w, q0.w);
        a1.x = __fadd_rn(a1.x, q1.x); a1.y = __fadd_rn(a1.y, q1.y);
        a1.z = __fadd_rn(a1.z, q1.z); a1.w = __fadd_rn(a1.w, q1.w);
    }
    // Part combine: c = a0 + a1 (elementwise, single binop).
    float c0 = __fadd_rn(a0.x, a1.x);
    float c1 = __fadd_rn(a0.y, a1.y);
    float c2 = __fadd_rn(a0.z, a1.z);
    float c3 = __fadd_rn(a0.w, a1.w);
    // NEON faddp horizontal reduce (adjacent pairs): (c0+c1) + (c2+c3).
    g_sum[r] = __fadd_rn(__fadd_rn(c0, c1), __fadd_rn(c2, c3));
}

// ---------------------------------------------------------------------------
// Kernel B: one block per query. Private top-16 per thread (packed
// (key_bits<<32)|idx so uint64 min == lexicographic (dist, index) min,
// matching top_k's tie-break), then a 16-round block-min merge feeding the
// class-vote histogram. key = d*d + 1e-6 is order-equivalent to the
// reference's sqrt(d*d + 1e-6) (sqrt strictly monotone; sqrt-collision ties
// need sub-ulp key gaps -> negligible).
//
// labels dtype detected at runtime: int64 labels have all-zero odd int32
// words; genuine int32 labels defeat the probe with P ~ 100^-32.
// ---------------------------------------------------------------------------
__global__ void knn_vote_kernel(const int* __restrict__ labels32, int N) {
    __shared__ unsigned long long list[BTHREADS * KSEL];   // 32 KB
    __shared__ unsigned long long red8[8];
    __shared__ int counts[NCLS];
    __shared__ int s_stride;                               // 1 = int32, 2 = int64

    int b   = blockIdx.x;
    int tid = threadIdx.x;
    float sx = g_sum[N + b];

    if (tid < NCLS) counts[tid] = 0;

    // Label dtype probe: warp 0 checks odd words 1,3,...,63.
    if (tid < 32) {
        int v = labels32[2 * tid + 1];
        unsigned any = __ballot_sync(0xffffffffu, v != 0);
        if (tid == 0) s_stride = (any == 0u) ? 2 : 1;
    }

    unsigned long long* my = &list[tid * KSEL];
    #pragma unroll
    for (int j = 0; j < KSEL; j++) my[j] = ~0ull;

    unsigned long long worst = ~0ull;
    int worstpos = 0;

    for (int i = tid; i < N; i += BTHREADS) {
        float d  = __fadd_rn(sx, -g_sum[i]);     // sx - sf, round-to-nearest
        float dd = __fmul_rn(d, d);
        float ky = __fadd_rn(dd, 1e-6f);
        unsigned long long pk =
            ((unsigned long long)__float_as_uint(ky) << 32) | (unsigned)i;
        if (pk < worst) {
            my[worstpos] = pk;
            worst = my[0]; worstpos = 0;
            #pragma unroll
            for (int j = 1; j < KSEL; j++) {
                unsigned long long v = my[j];
                if (v > worst) { worst = v; worstpos = j; }
            }
        }
    }

    // Sort my 16 ascending (tiny insertion sort).
    #pragma unroll
    for (int i = 1; i < KSEL; i++) {
        unsigned long long key = my[i];
        int j = i - 1;
        while (j >= 0 && my[j] > key) { my[j + 1] = my[j]; j--; }
        my[j + 1] = key;
    }
    __syncthreads();
    int lstride = s_stride;

    // 16-round global merge: block-min of per-thread heads.
    int ptr = 0;
    for (int r = 0; r < KSEL; r++) {
        unsigned long long v = (ptr < KSEL) ? my[ptr] : ~0ull;
        unsigned long long w = v;
        #pragma unroll
        for (int off = 16; off; off >>= 1) {
            unsigned long long u = __shfl_xor_sync(0xffffffffu, w, off);
            w = (u < w) ? u : w;
        }
        if ((tid & 31) == 0) red8[tid >> 5] = w;
        __syncthreads();
        unsigned long long m = red8[0];
        #pragma unroll
        for (int j = 1; j < 8; j++) { unsigned long long u = red8[j]; m = (u < m) ? u : m; }
        if (v == m) ptr++;                       // unique keys -> exactly one advances
        if (tid == 0) {
            int idx = (int)(unsigned)(m & 0xffffffffull);
            int lab = labels32[(size_t)idx * lstride];   // low word if int64
            if (lab < 0 || lab >= NCLS) lab = 0;          // hard clamp: no smem OOB
            counts[lab]++;
        }
        __syncthreads();
    }

    // Vote: first max (== jnp.argmax) -> strict '>' scan.
    if (tid == 0) {
        int best = 0, bc = -1;
        #pragma unroll 4
        for (int c = 0; c < NCLS; c++) {
            int v = counts[c];
            if (v > bc) { bc = v; best = c; }
        }
        g_cls[b] = best;
    }
}

// ---------------------------------------------------------------------------
// Kernel C: out[i][j] = (float)cls[j]. Output buffer is FLOAT32 (proven R8).
// ---------------------------------------------------------------------------
__global__ void fill_out_kernel(float* __restrict__ out, int B) {
    int j = threadIdx.x;
    int i = blockIdx.x;
    if (j < B) out[(size_t)i * B + j] = (float)g_cls[j];
}

extern "C" void kernel_launch(void* const* d_in, const int* in_sizes, int n_in,
                              void* d_out, int out_size) {
    const float* x        = (const float*)d_in[0];
    const float* features = (const float*)d_in[1];
    const int*   labels32 = (const int*)d_in[2];
    int B = in_sizes[0] / FEAT;   // 512
    int N = in_sizes[2];          // 100000

    int rows = N + B;
    row_sums_kernel<<<(rows + 255) / 256, 256>>>(x, features, N, B);
    knn_vote_kernel<<<B, BTHREADS>>>(labels32, N);
    fill_out_kernel<<<B, B>>>((float*)d_out, B);
}